// round 12
// baseline (speedup 1.0000x reference)
#include <cuda_runtime.h>

// Problem constants
#define BB 8
#define NN 1024
#define FF 2048
#define CC 4
#define NTOK (BB * NN)            // 8192 tokens
#define VEC_ELEMS (BB * NN * FF)  // 16777216 floats
#define BCN (BB * CC)             // 32 (b,c) pairs

// k2 smem layout (dynamic): weights 64 KB | v-buffers 128 KB | 32 mbarriers
#define K2_SW_BYTES 65536
#define K2_V_BYTES 131072
#define K2_MBAR_OFF (K2_SW_BYTES + K2_V_BYTES)      // 196608
#define K2_SMEM_TOTAL (K2_MBAR_OFF + 256)           // 196864

// Scratch (static device globals — no allocation allowed)
__device__ float g_Wpart[32][8][2048];  // [h-chunk][row r][f], r = c + 4*half
__device__ float g_W[8 * 2048];         // Weff rows: r<4 -> Wa[c], r>=4 -> Wb[c]
__device__ float g_cst[4];              // W2 @ b1 + b2
__device__ float g_EA[BCN * NN];        // exp(p1[b,n,c] + const[c])
__device__ float g_EB[BCN * NN];        // exp(p2[b,n,c])

// Packed fp32x2 FMA: acc.(lo,hi) += v.(lo,hi) * w.(lo,hi)   (Blackwell f32x2)
__device__ __forceinline__ void fma2(unsigned long long& a,
                                     unsigned long long v,
                                     unsigned long long w) {
    asm("fma.rn.f32x2 %0, %1, %2, %0;" : "+l"(a) : "l"(v), "l"(w));
}

__device__ __forceinline__ unsigned smem_u32(const void* p) {
    unsigned a;
    asm("{ .reg .u64 t; cvta.to.shared.u64 t, %1; cvt.u32.u64 %0, t; }"
        : "=r"(a) : "l"(p));
    return a;
}

__device__ __forceinline__ void mbar_init(unsigned mbar, unsigned cnt) {
    asm volatile("mbarrier.init.shared.b64 [%0], %1;" :: "r"(mbar), "r"(cnt)
                 : "memory");
}
__device__ __forceinline__ void mbar_expect_tx(unsigned mbar, unsigned bytes) {
    asm volatile("mbarrier.arrive.expect_tx.shared.b64 _, [%0], %1;"
                 :: "r"(mbar), "r"(bytes) : "memory");
}
__device__ __forceinline__ void mbar_wait(unsigned mbar, unsigned parity) {
    asm volatile(
        "{\n\t"
        ".reg .pred P;\n\t"
        "WL_%=:\n\t"
        "mbarrier.try_wait.parity.acquire.cta.shared::cta.b64 P, [%0], %1, 0x989680;\n\t"
        "@P bra.uni WD_%=;\n\t"
        "bra.uni WL_%=;\n\t"
        "WD_%=:\n\t"
        "}" :: "r"(mbar), "r"(parity) : "memory");
}
__device__ __forceinline__ void bulk_g2s(unsigned dst_smem, const void* src,
                                         unsigned bytes, unsigned mbar) {
    asm volatile(
        "cp.async.bulk.shared::cta.global.mbarrier::complete_tx::bytes "
        "[%0], [%1], %2, [%3];"
        :: "r"(dst_smem), "l"(src), "r"(bytes), "r"(mbar) : "memory");
}
__device__ __forceinline__ void bulk_s2g(void* dst, unsigned src_smem,
                                         unsigned bytes) {
    asm volatile("cp.async.bulk.global.shared::cta.bulk_group [%0], [%1], %2;"
                 :: "l"(dst), "r"(src_smem), "r"(bytes) : "memory");
}

// ---------------------------------------------------------------------------
// Kernel 1: partial Weff[r][f] = sum_{h in 32-chunk} W2[c][h] * W1[h][f']
// ---------------------------------------------------------------------------
__global__ void k1_weff_part(const float* __restrict__ W1,
                             const float* __restrict__ W2) {
    __shared__ float sW2[4 * 32];
    const int tid = threadIdx.x;
    const int h0 = blockIdx.y * 32;
    if (tid < 128) sW2[tid] = W2[(tid >> 5) * 1024 + h0 + (tid & 31)];
    __syncthreads();

    const int fp = blockIdx.x * 256 + tid;  // 0..4095 (column of W1)
    float a0 = 0.f, a1 = 0.f, a2 = 0.f, a3 = 0.f;
    const float* w1p = W1 + (size_t)h0 * 4096 + fp;
#pragma unroll
    for (int hh = 0; hh < 32; hh++) {
        float w1 = w1p[(size_t)hh * 4096];
        a0 = fmaf(sW2[hh], w1, a0);
        a1 = fmaf(sW2[32 + hh], w1, a1);
        a2 = fmaf(sW2[64 + hh], w1, a2);
        a3 = fmaf(sW2[96 + hh], w1, a3);
    }
    const int half = fp >> 11;
    const int f = fp & 2047;
    const int rb = half * 4;
    g_Wpart[blockIdx.y][rb + 0][f] = a0;
    g_Wpart[blockIdx.y][rb + 1][f] = a1;
    g_Wpart[blockIdx.y][rb + 2][f] = a2;
    g_Wpart[blockIdx.y][rb + 3][f] = a3;
}

// ---------------------------------------------------------------------------
// Kernel 1b: reduce partials into g_W; one warp also computes g_cst
// ---------------------------------------------------------------------------
__global__ void k1b_reduce(const float* __restrict__ W2,
                           const float* __restrict__ b1,
                           const float* __restrict__ b2) {
    const int idx = blockIdx.x * 256 + threadIdx.x;  // 0..16383
    const int r = idx >> 11, f = idx & 2047;
    float s = 0.f;
#pragma unroll
    for (int p = 0; p < 32; p++) s += g_Wpart[p][r][f];
    g_W[r * 2048 + f] = s;

    if (blockIdx.x == 0 && threadIdx.x < 32) {
        const int lane = threadIdx.x;
        float c0 = 0.f, c1 = 0.f, c2 = 0.f, c3 = 0.f;
        for (int h = lane; h < 1024; h += 32) {
            float bv = b1[h];
            c0 = fmaf(W2[h], bv, c0);
            c1 = fmaf(W2[1024 + h], bv, c1);
            c2 = fmaf(W2[2048 + h], bv, c2);
            c3 = fmaf(W2[3072 + h], bv, c3);
        }
#pragma unroll
        for (int off = 16; off; off >>= 1) {
            c0 += __shfl_xor_sync(~0u, c0, off);
            c1 += __shfl_xor_sync(~0u, c1, off);
            c2 += __shfl_xor_sync(~0u, c2, off);
            c3 += __shfl_xor_sync(~0u, c3, off);
        }
        if (lane == 0) {
            g_cst[0] = c0 + b2[0];
            g_cst[1] = c1 + b2[1];
            g_cst[2] = c2 + b2[2];
            g_cst[3] = c3 + b2[3];
        }
    }
}

// ---------------------------------------------------------------------------
// Kernel 2 (R12): TMA-bulk edition. The 128 MB copy stream rides the async
// proxy: cp.async.bulk G->S fills 4 single-use 4 KB buffers per warp (all
// loads issued up front: 16 KB in flight/warp), FMAs read v+W from smem,
// cp.async.bulk S->G drains each buffer to out. Warps never issue LDG/STG
// for bulk data. 2 tokens/warp, grid 512, 1 block/SM (192 KB smem).
// ---------------------------------------------------------------------------
__global__ void __launch_bounds__(256)
k2_proj(const char* __restrict__ vec_raw, char* __restrict__ out_raw) {
    extern __shared__ char smem[];
    const unsigned sbase = smem_u32(smem);
    ulonglong2* sW = reinterpret_cast<ulonglong2*>(smem);

    const int tid = threadIdx.x;
    const int lane = tid & 31;
    const int wid = tid >> 5;
    const int t0 = (blockIdx.x * 8 + wid) * 2;

    const char* gv = vec_raw + (size_t)t0 * 8192;  // this warp's 16 KB
    char* go = out_raw + (size_t)t0 * 8192;

    // Init 32 mbarriers (4 per warp), then issue ALL bulk loads.
    if (tid < 32) mbar_init(sbase + K2_MBAR_OFF + tid * 8, 1);
    __syncthreads();

    const unsigned my_sv = sbase + K2_SW_BYTES + wid * 16384;  // 4 x 4 KB
    const unsigned my_mb = sbase + K2_MBAR_OFF + wid * 32;     // 4 x 8 B

    if (lane == 0) {
#pragma unroll
        for (int ch = 0; ch < 4; ch++) {
            const unsigned mb = my_mb + ch * 8;
            mbar_expect_tx(mb, 4096);
            // token0 + token1 slices of k-steps [4ch, 4ch+4)
            bulk_g2s(my_sv + ch * 4096, gv + ch * 2048, 2048, mb);
            bulk_g2s(my_sv + ch * 4096 + 2048, gv + 8192 + ch * 2048, 2048, mb);
        }
    }

    // Stage weights (overlaps with in-flight bulk loads).
    const ulonglong2* gWu = reinterpret_cast<const ulonglong2*>(g_W);
    for (int s = tid; s < 4096; s += 256) sW[s] = gWu[s];
    __syncthreads();

    unsigned long long acc[8][2];  // f32x2 partial sums
#pragma unroll
    for (int r = 0; r < 8; r++) {
        acc[r][0] = 0ull;
        acc[r][1] = 0ull;
    }

#pragma unroll
    for (int ch = 0; ch < 4; ch++) {
        mbar_wait(my_mb + ch * 8, 0);
        const ulonglong2* bv0 = reinterpret_cast<const ulonglong2*>(
            smem + K2_SW_BYTES + wid * 16384 + ch * 4096);
        const ulonglong2* bv1 = bv0 + 128;  // +2048 B
#pragma unroll
        for (int u = 0; u < 4; u++) {
            const int li = 32 * u + lane;        // 0..127 within chunk
            const int i = 128 * ch + li;         // global f4 index 0..511
            const ulonglong2 v0 = bv0[li];
            const ulonglong2 v1 = bv1[li];
#pragma unroll
            for (int r = 0; r < 8; r++) {
                const ulonglong2 w = sW[r * 512 + i];
                fma2(acc[r][0], v0.x, w.x);
                fma2(acc[r][0], v0.y, w.y);
                fma2(acc[r][1], v1.x, w.x);
                fma2(acc[r][1], v1.y, w.y);
            }
        }
        // Drain this buffer to out via async bulk store.
        if (lane == 0) {
            bulk_s2g(go + ch * 2048, my_sv + ch * 4096, 2048);
            bulk_s2g(go + 8192 + ch * 2048, my_sv + ch * 4096 + 2048, 2048);
            asm volatile("cp.async.bulk.commit_group;" ::: "memory");
        }
    }

    // Horizontal: f32x2 -> scalar, then warp reduce.
    float facc[8][2];
#pragma unroll
    for (int r = 0; r < 8; r++)
#pragma unroll
        for (int t = 0; t < 2; t++) {
            float2 p = *reinterpret_cast<float2*>(&acc[r][t]);
            float s = p.x + p.y;
#pragma unroll
            for (int off = 16; off; off >>= 1)
                s += __shfl_xor_sync(~0u, s, off);
            facc[r][t] = s;
        }

    if (lane == 0) {
#pragma unroll
        for (int t = 0; t < 2; t++) {
            const int token = t0 + t;
            const int b = token >> 10, n = token & 1023;
            const int base = b * 4 * 1024 + n;
#pragma unroll
            for (int c = 0; c < 4; c++) {
                g_EA[base + c * 1024] = __expf(facc[c][t] + g_cst[c]);
                g_EB[base + c * 1024] = __expf(facc[4 + c][t]);
            }
        }
        // Ensure all bulk stores are complete before kernel end.
        asm volatile("cp.async.bulk.wait_group 0;" ::: "memory");
    }
}

// ---------------------------------------------------------------------------
// Kernel 3 (R8 version — best measured): connections = t/(1+t)
// grid (64, 32): 16-row m tiles.
// ---------------------------------------------------------------------------
__global__ void k3_conn(float4* __restrict__ conn4) {
    const int tid = threadIdx.x;
    const int bc = blockIdx.y;
    const int m0 = blockIdx.x * 16;

    const float4* ea4 = reinterpret_cast<const float4*>(g_EA);
    const float4* eb4 = reinterpret_cast<const float4*>(g_EB);
    float4 ea = __ldg(&ea4[bc * 256 + tid]);

    float4 e0 = __ldg(&eb4[(bc * 1024 + m0) / 4 + 0]);
    float4 e1 = __ldg(&eb4[(bc * 1024 + m0) / 4 + 1]);
    float4 e2 = __ldg(&eb4[(bc * 1024 + m0) / 4 + 2]);
    float4 e3 = __ldg(&eb4[(bc * 1024 + m0) / 4 + 3]);
    float ebv[16] = {e0.x, e0.y, e0.z, e0.w, e1.x, e1.y, e1.z, e1.w,
                     e2.x, e2.y, e2.z, e2.w, e3.x, e3.y, e3.z, e3.w};

    size_t obase = ((size_t)bc * 1024 + m0) * 256 + tid;
#pragma unroll
    for (int j = 0; j < 16; j++) {
        const float eb = ebv[j];
        float4 o;
        float t;
        t = ea.x * eb; o.x = __fdividef(t, 1.0f + t);
        t = ea.y * eb; o.y = __fdividef(t, 1.0f + t);
        t = ea.z * eb; o.z = __fdividef(t, 1.0f + t);
        t = ea.w * eb; o.w = __fdividef(t, 1.0f + t);
        __stcs(&conn4[obase + (size_t)j * 256], o);
    }
}

// ---------------------------------------------------------------------------
extern "C" void kernel_launch(void* const* d_in, const int* in_sizes, int n_in,
                              void* d_out, int out_size) {
    const float* vectors = (const float*)d_in[0];
    const float* W1 = (const float*)d_in[1];
    const float* b1 = (const float*)d_in[2];
    const float* W2 = (const float*)d_in[3];
    const float* b2 = (const float*)d_in[4];
    float* out = (float*)d_out;

    cudaFuncSetAttribute(k2_proj, cudaFuncAttributeMaxDynamicSharedMemorySize,
                         K2_SMEM_TOTAL);

    k1_weff_part<<<dim3(16, 32), 256>>>(W1, W2);
    k1b_reduce<<<64, 256>>>(W2, b1, b2);
    k2_proj<<<512, 256, K2_SMEM_TOTAL>>>((const char*)vectors, (char*)out);
    k3_conn<<<dim3(64, 32), 256>>>((float4*)(out + VEC_ELEMS));
}

// round 13
// speedup vs baseline: 1.3389x; 1.3389x over previous
#include <cuda_runtime.h>

// Problem constants
#define BB 8
#define NN 1024
#define FF 2048
#define CC 4
#define NTOK (BB * NN)            // 8192 tokens
#define VEC_ELEMS (BB * NN * FF)  // 16777216 floats
#define BCN (BB * CC)             // 32 (b,c) pairs
#define K2_TILES 512              // 16 tokens per tile
#define K2_BLOCKS 296             // 148 SMs x 2 blocks

// Scratch (static device globals — no allocation allowed)
__device__ float g_Wpart[32][8][2048];  // [h-chunk][row r][f], r = c + 4*half
__device__ float g_W[8 * 2048];         // Weff rows: r<4 -> Wa[c], r>=4 -> Wb[c]
__device__ float g_cst[4];              // W2 @ b1 + b2
__device__ float g_EA[BCN * NN];        // exp(p1[b,n,c] + const[c])
__device__ float g_EB[BCN * NN];        // exp(p2[b,n,c])
__device__ int g_ctr;                   // k2 work-stealing tile counter

// Packed fp32x2 FMA: acc.(lo,hi) += v.(lo,hi) * w.(lo,hi)   (Blackwell f32x2)
__device__ __forceinline__ void fma2(unsigned long long& a,
                                     unsigned long long v,
                                     unsigned long long w) {
    asm("fma.rn.f32x2 %0, %1, %2, %0;" : "+l"(a) : "l"(v), "l"(w));
}

// ---------------------------------------------------------------------------
// Kernel 1: partial Weff[r][f] = sum_{h in 32-chunk} W2[c][h] * W1[h][f']
// ---------------------------------------------------------------------------
__global__ void k1_weff_part(const float* __restrict__ W1,
                             const float* __restrict__ W2) {
    __shared__ float sW2[4 * 32];
    const int tid = threadIdx.x;
    const int h0 = blockIdx.y * 32;
    if (tid < 128) sW2[tid] = W2[(tid >> 5) * 1024 + h0 + (tid & 31)];
    __syncthreads();

    const int fp = blockIdx.x * 256 + tid;  // 0..4095 (column of W1)
    float a0 = 0.f, a1 = 0.f, a2 = 0.f, a3 = 0.f;
    const float* w1p = W1 + (size_t)h0 * 4096 + fp;
#pragma unroll
    for (int hh = 0; hh < 32; hh++) {
        float w1 = w1p[(size_t)hh * 4096];
        a0 = fmaf(sW2[hh], w1, a0);
        a1 = fmaf(sW2[32 + hh], w1, a1);
        a2 = fmaf(sW2[64 + hh], w1, a2);
        a3 = fmaf(sW2[96 + hh], w1, a3);
    }
    const int half = fp >> 11;
    const int f = fp & 2047;
    const int rb = half * 4;
    g_Wpart[blockIdx.y][rb + 0][f] = a0;
    g_Wpart[blockIdx.y][rb + 1][f] = a1;
    g_Wpart[blockIdx.y][rb + 2][f] = a2;
    g_Wpart[blockIdx.y][rb + 3][f] = a3;
}

// ---------------------------------------------------------------------------
// Kernel 1b: reduce partials into g_W; computes g_cst; resets k2 counter
// ---------------------------------------------------------------------------
__global__ void k1b_reduce(const float* __restrict__ W2,
                           const float* __restrict__ b1,
                           const float* __restrict__ b2) {
    const int idx = blockIdx.x * 256 + threadIdx.x;  // 0..16383
    const int r = idx >> 11, f = idx & 2047;
    float s = 0.f;
#pragma unroll
    for (int p = 0; p < 32; p++) s += g_Wpart[p][r][f];
    g_W[r * 2048 + f] = s;

    if (blockIdx.x == 0 && threadIdx.x == 32) g_ctr = 0;  // reset work queue

    if (blockIdx.x == 0 && threadIdx.x < 32) {
        const int lane = threadIdx.x;
        float c0 = 0.f, c1 = 0.f, c2 = 0.f, c3 = 0.f;
        for (int h = lane; h < 1024; h += 32) {
            float bv = b1[h];
            c0 = fmaf(W2[h], bv, c0);
            c1 = fmaf(W2[1024 + h], bv, c1);
            c2 = fmaf(W2[2048 + h], bv, c2);
            c3 = fmaf(W2[3072 + h], bv, c3);
        }
#pragma unroll
        for (int off = 16; off; off >>= 1) {
            c0 += __shfl_xor_sync(~0u, c0, off);
            c1 += __shfl_xor_sync(~0u, c1, off);
            c2 += __shfl_xor_sync(~0u, c2, off);
            c3 += __shfl_xor_sync(~0u, c3, off);
        }
        if (lane == 0) {
            g_cst[0] = c0 + b2[0];
            g_cst[1] = c1 + b2[1];
            g_cst[2] = c2 + b2[2];
            g_cst[3] = c3 + b2[3];
        }
    }
}

// ---------------------------------------------------------------------------
// Kernel 2 (R13): PERSISTENT version of the proven R8 kernel.
// 296 blocks (2/SM) stage weights ONCE, then work-steal 16-token tiles from
// a global counter — removes the 1.73-wave tail and re-staging traffic.
// Per tile: 2 tokens/warp, 4-step chunks double-buffered (8 LDG.128 in
// flight), packed f32x2 FMAs, fused streaming copy.
// ---------------------------------------------------------------------------
__global__ void __launch_bounds__(256, 2)
k2_proj(const ulonglong2* __restrict__ vecu, ulonglong2* __restrict__ outu) {
    extern __shared__ ulonglong2 sW[];  // 4096 * 16 B = 64 KB = all of g_W
    __shared__ int s_tile;

    const int tid = threadIdx.x;
    const int lane = tid & 31;
    const int wid = tid >> 5;

    // Stage weights once per block.
    const ulonglong2* gWu = reinterpret_cast<const ulonglong2*>(g_W);
    for (int s = tid; s < 4096; s += 256) sW[s] = gWu[s];

    for (;;) {
        __syncthreads();  // protect s_tile (and first-iter weight staging)
        if (tid == 0) s_tile = atomicAdd(&g_ctr, 1);
        __syncthreads();
        const int tile = s_tile;
        if (tile >= K2_TILES) break;

        const int t0 = (tile * 8 + wid) * 2;
        const ulonglong2* vp = vecu + (size_t)t0 * 512;
        ulonglong2* op = outu + (size_t)t0 * 512;

        ulonglong2 va[2][4], vb[2][4];
#pragma unroll
        for (int u = 0; u < 4; u++) {
            va[0][u] = __ldcs(&vp[lane + 32 * u]);
            vb[0][u] = __ldcs(&vp[512 + lane + 32 * u]);
        }

        unsigned long long acc[8][2];
#pragma unroll
        for (int r = 0; r < 8; r++) {
            acc[r][0] = 0ull;
            acc[r][1] = 0ull;
        }

#pragma unroll
        for (int ch = 0; ch < 4; ch++) {
            const int cur = ch & 1, nxt = cur ^ 1;
            const int base = lane + 128 * ch;
            if (ch < 3) {
#pragma unroll
                for (int u = 0; u < 4; u++) {
                    va[nxt][u] = __ldcs(&vp[base + 128 + 32 * u]);
                    vb[nxt][u] = __ldcs(&vp[512 + base + 128 + 32 * u]);
                }
            }
#pragma unroll
            for (int u = 0; u < 4; u++) {
                const int i = base + 32 * u;
                const ulonglong2 v0 = va[cur][u];
                const ulonglong2 v1 = vb[cur][u];
#pragma unroll
                for (int r = 0; r < 8; r++) {
                    const ulonglong2 w = sW[r * 512 + i];
                    fma2(acc[r][0], v0.x, w.x);
                    fma2(acc[r][0], v0.y, w.y);
                    fma2(acc[r][1], v1.x, w.x);
                    fma2(acc[r][1], v1.y, w.y);
                }
            }
            // Fused streaming copy, issued after the FMA block.
#pragma unroll
            for (int u = 0; u < 4; u++) {
                __stcs(&op[base + 32 * u], va[cur][u]);
                __stcs(&op[512 + base + 32 * u], vb[cur][u]);
            }
        }

        float facc[8][2];
#pragma unroll
        for (int r = 0; r < 8; r++)
#pragma unroll
            for (int t = 0; t < 2; t++) {
                float2 p = *reinterpret_cast<float2*>(&acc[r][t]);
                float s = p.x + p.y;
#pragma unroll
                for (int off = 16; off; off >>= 1)
                    s += __shfl_xor_sync(~0u, s, off);
                facc[r][t] = s;
            }

        if (lane == 0) {
#pragma unroll
            for (int t = 0; t < 2; t++) {
                const int token = t0 + t;
                const int b = token >> 10, n = token & 1023;
                const int base = b * 4 * 1024 + n;
#pragma unroll
                for (int c = 0; c < 4; c++) {
                    g_EA[base + c * 1024] = __expf(facc[c][t] + g_cst[c]);
                    g_EB[base + c * 1024] = __expf(facc[4 + c][t]);
                }
            }
        }
    }
}

// ---------------------------------------------------------------------------
// Kernel 3 (R8 version — best measured): connections = t/(1+t)
// grid (64, 32): 16-row m tiles.
// ---------------------------------------------------------------------------
__global__ void k3_conn(float4* __restrict__ conn4) {
    const int tid = threadIdx.x;
    const int bc = blockIdx.y;
    const int m0 = blockIdx.x * 16;

    const float4* ea4 = reinterpret_cast<const float4*>(g_EA);
    const float4* eb4 = reinterpret_cast<const float4*>(g_EB);
    float4 ea = __ldg(&ea4[bc * 256 + tid]);

    float4 e0 = __ldg(&eb4[(bc * 1024 + m0) / 4 + 0]);
    float4 e1 = __ldg(&eb4[(bc * 1024 + m0) / 4 + 1]);
    float4 e2 = __ldg(&eb4[(bc * 1024 + m0) / 4 + 2]);
    float4 e3 = __ldg(&eb4[(bc * 1024 + m0) / 4 + 3]);
    float ebv[16] = {e0.x, e0.y, e0.z, e0.w, e1.x, e1.y, e1.z, e1.w,
                     e2.x, e2.y, e2.z, e2.w, e3.x, e3.y, e3.z, e3.w};

    size_t obase = ((size_t)bc * 1024 + m0) * 256 + tid;
#pragma unroll
    for (int j = 0; j < 16; j++) {
        const float eb = ebv[j];
        float4 o;
        float t;
        t = ea.x * eb; o.x = __fdividef(t, 1.0f + t);
        t = ea.y * eb; o.y = __fdividef(t, 1.0f + t);
        t = ea.z * eb; o.z = __fdividef(t, 1.0f + t);
        t = ea.w * eb; o.w = __fdividef(t, 1.0f + t);
        __stcs(&conn4[obase + (size_t)j * 256], o);
    }
}

// ---------------------------------------------------------------------------
extern "C" void kernel_launch(void* const* d_in, const int* in_sizes, int n_in,
                              void* d_out, int out_size) {
    const float* vectors = (const float*)d_in[0];
    const float* W1 = (const float*)d_in[1];
    const float* b1 = (const float*)d_in[2];
    const float* W2 = (const float*)d_in[3];
    const float* b2 = (const float*)d_in[4];
    float* out = (float*)d_out;

    cudaFuncSetAttribute(k2_proj, cudaFuncAttributeMaxDynamicSharedMemorySize,
                         64 * 1024);

    k1_weff_part<<<dim3(16, 32), 256>>>(W1, W2);
    k1b_reduce<<<64, 256>>>(W2, b1, b2);
    k2_proj<<<K2_BLOCKS, 256, 64 * 1024>>>((const ulonglong2*)vectors,
                                           (ulonglong2*)out);
    k3_conn<<<dim3(64, 32), 256>>>((float4*)(out + VEC_ELEMS));
}